// round 16
// baseline (speedup 1.0000x reference)
#include <cuda_runtime.h>
#include <cuda_fp16.h>
#include <math.h>
#include <stdint.h>

#define D   256
#define NA  16
#define NC  256

// ---------------------------------------------------------------------------
// Scratch (device globals — no allocation allowed in kernel_launch)
// ---------------------------------------------------------------------------
__device__ __half g_qads[8192u  * 256u];   // qm_ads = h_ads@G1 + w1
__device__ __half g_tads[8192u  * 256u];   // t_ads  = h_ads@G2
__device__ __half g_vads[8192u  * 256u];
__device__ __half g_vcat[131072u * 256u];
__device__ __half gx_ads[8192u  * 256u];
__device__ __half gx_cat[131072u * 256u];
__device__ __half gw_v[2u * 65536u];       // Wv_a, Wv_c fp16
__device__ __half gW1h[65536u];            // W1[m,j] = sum_i Wk_c[i,m] Wq_a[i,j]
__device__ __half gW2h[65536u];            // W2[m,j] = sum_i Wq_c[i,m] Wk_a[i,j]
__device__ float  g_w1[256];               // w1[m] = sum_i bq_a[i] Wk_c[i,m]
__device__ float  g_w2[256];               // w2[j] = sum_i bq_c[i] Wk_a[i,j]
__device__ float  g_zero[256];             // zero bias (static zero-init)
__device__ float  g_beta2[8192];           // beta2[a] = h_a . w2

struct GemmArgs {
    const __half* X[4];
    const __half* W[4];
    const float*  bias[4];
    __half*       Y[4];
};
struct WprodArgs {
    const float* A[2];
    const float* B[2];
    const float* bA[2];
    float*       wA[2];
    const float* bB[2];
    float*       wB[2];
    __half*      P[2];
};

// ---------------------------------------------------------------------------
// PTX helpers (arch-neutral sm_80+ — harness ptxas target is plain sm_103)
// ---------------------------------------------------------------------------
__device__ __forceinline__ uint32_t smem_u32(const void* p) {
    uint32_t a;
    asm("{ .reg .u64 t; cvta.to.shared.u64 t, %1; cvt.u32.u64 %0, t; }"
        : "=r"(a) : "l"(p));
    return a;
}
__device__ __forceinline__ void cpa16(uint32_t dst, const void* src) {
    asm volatile("cp.async.ca.shared.global [%0], [%1], 16;"
                 :: "r"(dst), "l"(src) : "memory");
}
__device__ __forceinline__ void ldm_x4(uint32_t* r, uint32_t addr) {
    asm volatile("ldmatrix.sync.aligned.m8n8.x4.shared.b16 {%0,%1,%2,%3}, [%4];"
                 : "=r"(r[0]), "=r"(r[1]), "=r"(r[2]), "=r"(r[3]) : "r"(addr));
}
__device__ __forceinline__ void mma16816h(float* c, const uint32_t* a,
                                          const uint32_t* b) {
    asm volatile(
        "mma.sync.aligned.m16n8k16.row.col.f32.f16.f16.f32 "
        "{%0,%1,%2,%3}, {%4,%5,%6,%7}, {%8,%9}, {%0,%1,%2,%3};"
        : "+f"(c[0]), "+f"(c[1]), "+f"(c[2]), "+f"(c[3])
        : "r"(a[0]), "r"(a[1]), "r"(a[2]), "r"(a[3]), "r"(b[0]), "r"(b[1]));
}
__device__ __forceinline__ uint32_t cvt2h(float a, float b) {
    uint32_t hp;
    asm("cvt.rn.f16x2.f32 %0, %1, %2;" : "=r"(hp) : "f"(b), "f"(a));
    return hp;
}
__device__ __forceinline__ float4 h4f(uint2 v) {
    __half2 h0 = *reinterpret_cast<__half2*>(&v.x);
    __half2 h1 = *reinterpret_cast<__half2*>(&v.y);
    float2 f0 = __half22float2(h0), f1 = __half22float2(h1);
    return make_float4(f0.x, f0.y, f1.x, f1.y);
}
__device__ __forceinline__ float dot4(float4 a, float4 b) {
    return a.x*b.x + a.y*b.y + a.z*b.z + a.w*b.w;
}

// ---------------------------------------------------------------------------
// Conversion prepass (merged ads+cat)
// ---------------------------------------------------------------------------
__global__ void __launch_bounds__(256)
conv_all(const float4* __restrict__ sa, uint2* __restrict__ da, int na4,
         const float4* __restrict__ sc, uint2* __restrict__ dc, int nc4)
{
    const int n = na4 + nc4;
    for (int i = blockIdx.x * blockDim.x + threadIdx.x; i < n;
         i += gridDim.x * blockDim.x) {
        if (i < na4) {
            float4 f = sa[i];
            da[i] = make_uint2(cvt2h(f.x, f.y), cvt2h(f.z, f.w));
        } else {
            float4 f = sc[i - na4];
            dc[i - na4] = make_uint2(cvt2h(f.x, f.y), cvt2h(f.z, f.w));
        }
    }
}

__global__ void __launch_bounds__(256)
conv_w(const float* w0, const float* w1, uint2* __restrict__ hi)
{
    const int z = blockIdx.y;
    const float* W = (z == 0) ? w0 : w1;
    const int i = blockIdx.x * 256 + threadIdx.x;
    float4 f = ((const float4*)W)[i];
    hi[z * 16384 + i] = make_uint2(cvt2h(f.x, f.y), cvt2h(f.z, f.w));
}

// ---------------------------------------------------------------------------
// Weight-products (both fused): P[m,j] = sum_i A[i,m] * B[i,j]
// ---------------------------------------------------------------------------
__global__ void __launch_bounds__(256)
wprod2(WprodArgs wa)
{
    const int z = blockIdx.y;
    const float* __restrict__ A = wa.A[z];
    const float* __restrict__ B = wa.B[z];
    __shared__ float As[256];
    const int m = blockIdx.x, j = threadIdx.x;

    As[j] = A[(size_t)j * 256 + m];
    __syncthreads();

    float a0 = 0.f, a1 = 0.f, a2 = 0.f, a3 = 0.f;
#pragma unroll 8
    for (int i = 0; i < 256; i += 4) {
        a0 += As[i]     * B[(size_t)i * 256 + j];
        a1 += As[i + 1] * B[(size_t)(i + 1) * 256 + j];
        a2 += As[i + 2] * B[(size_t)(i + 2) * 256 + j];
        a3 += As[i + 3] * B[(size_t)(i + 3) * 256 + j];
    }
    wa.P[z][(size_t)m * 256 + j] = __float2half((a0 + a1) + (a2 + a3));

    if (wa.wA[z] && j == 0) {
        const float* bA = wa.bA[z];
        float s = 0.f;
        for (int i = 0; i < 256; i++) s += bA[i] * As[i];
        wa.wA[z][m] = s;
    }
    if (wa.wB[z] && m == 0) {
        const float* bB = wa.bB[z];
        float s0 = 0.f, s1 = 0.f, s2 = 0.f, s3 = 0.f;
#pragma unroll 8
        for (int i = 0; i < 256; i += 4) {
            s0 += bB[i]     * B[(size_t)i * 256 + j];
            s1 += bB[i + 1] * B[(size_t)(i + 1) * 256 + j];
            s2 += bB[i + 2] * B[(size_t)(i + 2) * 256 + j];
            s3 += bB[i + 3] * B[(size_t)(i + 3) * 256 + j];
        }
        wa.wB[z][j] = (s0 + s1) + (s2 + s3);
    }
}

// ---------------------------------------------------------------------------
// beta2[a] = h_ads[a] . w2   (warp per row)
// ---------------------------------------------------------------------------
__global__ void __launch_bounds__(256)
beta2_kernel(const __half* __restrict__ x, const float* __restrict__ w2,
             float* __restrict__ beta2)
{
    const int warp = threadIdx.x >> 5, l = threadIdx.x & 31;
    const int row = blockIdx.x * 8 + warp;
    const uint2* xr = (const uint2*)(x + (size_t)row * 256);
    float4 a = h4f(xr[l]), b = h4f(xr[32 + l]);
    float4 wa = *(const float4*)(w2 + 4 * l);
    float4 wb = *(const float4*)(w2 + 128 + 4 * l);
    float s = dot4(a, wa) + dot4(b, wb);
#pragma unroll
    for (int o = 16; o > 0; o >>= 1) s += __shfl_xor_sync(0xffffffffu, s, o);
    if (l == 0) beta2[row] = s;
}

// ---------------------------------------------------------------------------
// Pipelined fp16 GEMM (4 fused problems: qm_ads / t_ads / v_ads / v_cat)
// ---------------------------------------------------------------------------
#define SMAT   16384u
#define SSTAGE 32768u
#define SWZ(row, ch) ((uint32_t)(row) * 128u + (((uint32_t)((ch) ^ ((row) & 7)) & 7u) << 4))

__global__ void __launch_bounds__(256, 2)
gemm_pipe(GemmArgs args)
{
    const int x    = blockIdx.x;
    const int widx = (x < 192) ? (x >> 6) : 3;
    const int mt   = (x < 192) ? (x & 63) : (x - 192);
    const __half* Xh   = args.X[widx];
    const __half* Whi  = args.W[widx];
    const float*  bias = args.bias[widx];
    __half*       Y    = args.Y[widx];

    extern __shared__ __align__(16) char smraw[];
    const uint32_t sb = smem_u32(smraw);

    const int tid  = threadIdx.x;
    const int lane = tid & 31;
    const int wid  = tid >> 5;
    const int wm   = wid & 3;
    const int wn   = wid >> 2;
    const int m0   = mt * 128;
    const int n0   = blockIdx.y * 128;

    float acc[2][8][4];
#pragma unroll
    for (int i = 0; i < 2; i++)
#pragma unroll
        for (int j = 0; j < 8; j++)
#pragma unroll
            for (int t = 0; t < 4; t++) acc[i][j][t] = 0.f;

#define ISSUE(stage, kk)                                                          \
    do {                                                                          \
        const uint32_t s = sb + (stage) * SSTAGE;                                 \
        _Pragma("unroll")                                                         \
        for (int i = 0; i < 4; i++) {                                             \
            const int idx = tid + 256 * i;                                        \
            const int row = idx >> 3, ch = idx & 7;                               \
            const uint32_t d = SWZ(row, ch);                                      \
            cpa16(s + 0*SMAT + d, Xh  + (size_t)(m0 + row) * 256 + (kk) + ch * 8);\
            cpa16(s + 1*SMAT + d, Whi + (size_t)(n0 + row) * 256 + (kk) + ch * 8);\
        }                                                                         \
        asm volatile("cp.async.commit_group;" ::: "memory");                      \
    } while (0)

    const int l15 = lane & 15, lhi = lane >> 4;
    uint32_t arowb[2], axor[2], browb[4], bxor[4];
#pragma unroll
    for (int i = 0; i < 2; i++) {
        uint32_t r = (uint32_t)(wm * 32 + i * 16 + l15);
        arowb[i] = r * 128u;
        axor[i] = r & 7u;
    }
#pragma unroll
    for (int bp = 0; bp < 4; bp++) {
        uint32_t r = (uint32_t)(wn * 64 + bp * 16 + l15);
        browb[bp] = r * 128u;
        bxor[bp] = r & 7u;
    }

    ISSUE(0, 0);
    ISSUE(1, 64);

#pragma unroll 1
    for (int c = 0; c < 4; c++) {
        if (c < 3)
            asm volatile("cp.async.wait_group 1;" ::: "memory");
        else
            asm volatile("cp.async.wait_group 0;" ::: "memory");
        __syncthreads();
        if (c + 2 < 4) ISSUE((c + 2) % 3, (c + 2) * 64);

        const uint32_t st = sb + (uint32_t)(c % 3) * SSTAGE;
#pragma unroll
        for (int ks = 0; ks < 4; ks++) {
            const uint32_t cb = (uint32_t)(ks * 2 + lhi);
            uint32_t ah[2][4], b[8][2], r[4];

#pragma unroll
            for (int i = 0; i < 2; i++)
                ldm_x4(ah[i], st + 0*SMAT + arowb[i] + (((cb ^ axor[i]) & 7u) << 4));
#pragma unroll
            for (int bp = 0; bp < 4; bp++) {
                ldm_x4(r, st + 1*SMAT + browb[bp] + (((cb ^ bxor[bp]) & 7u) << 4));
                b[2*bp][0] = r[0]; b[2*bp+1][0] = r[1];
                b[2*bp][1] = r[2]; b[2*bp+1][1] = r[3];
            }
#pragma unroll
            for (int am = 0; am < 2; am++)
#pragma unroll
                for (int bn = 0; bn < 8; bn++) mma16816h(acc[am][bn], ah[am], b[bn]);
        }
    }

    const int orow  = m0 + wm * 32 + (lane >> 2);
    const int ocol0 = n0 + wn * 64 + (lane & 3) * 2;
#pragma unroll
    for (int am = 0; am < 2; am++) {
#pragma unroll
        for (int bn = 0; bn < 8; bn++) {
            const int col = ocol0 + bn * 8;
            float2 bv = *(const float2*)(bias + col);
            uint32_t p0 = cvt2h(acc[am][bn][0] + bv.x, acc[am][bn][1] + bv.y);
            uint32_t p1 = cvt2h(acc[am][bn][2] + bv.x, acc[am][bn][3] + bv.y);
            *(uint32_t*)(Y + (size_t)(orow + am * 16)     * 256 + col) = p0;
            *(uint32_t*)(Y + (size_t)(orow + am * 16 + 8) * 256 + col) = p1;
        }
    }
}

// ---------------------------------------------------------------------------
// Ads attention v3: 2 blocks per graph, 8 queries each.
// blockIdx.x = b*2 + qh. smem: Qs[8][260] | Ps[8][260]
// ---------------------------------------------------------------------------
__global__ void __launch_bounds__(256, 2)
attn_ads(const __half* __restrict__ q, const __half* __restrict__ k,
         const __half* __restrict__ v, const float* __restrict__ h,
         float* __restrict__ out)
{
    extern __shared__ __align__(16) float sm[];
    float* Qs = sm;             // 8 x 260
    float* Ps = sm + 8 * 260;   // 8 x 260
    const int b   = blockIdx.x >> 1;
    const int qh  = blockIdx.x & 1;
    const int tid = threadIdx.x;
    const float scale = 0.0625f;
    const int qrow0 = b * NA + qh * 8;   // first global query row

    // load Q (8 x 256 halves) -> fp32 smem
    {
        const uint2* src = (const uint2*)(q + (size_t)qrow0 * D);
#pragma unroll
        for (int h2 = 0; h2 < 2; h2++) {
            int i = tid + h2 * 256;      // 0..511
            int row = i >> 6, col = (i & 63) << 2;
            float4 vv = h4f(src[i]);
            float* d = Qs + row * 260 + col;
            d[0] = vv.x; d[1] = vv.y; d[2] = vv.z; d[3] = vv.w;
        }
    }
    __syncthreads();

    const int w = tid >> 5, l = tid & 31;
    const int g = l >> 3, t = l & 7;

    // scores: warp w owns keys w*32 + g*4 .. +3; lane t owns dims 32c+4t
    {
        const int kbase = w * 32 + g * 4;
        float s[8][4];
#pragma unroll
        for (int qi = 0; qi < 8; qi++)
#pragma unroll
            for (int kk = 0; kk < 4; kk++) s[qi][kk] = 0.f;

#pragma unroll
        for (int c = 0; c < 8; c++) {
            const int d0 = 32 * c + 4 * t;
            float4 kf[4];
#pragma unroll
            for (int kk = 0; kk < 4; kk++)
                kf[kk] = h4f(*(const uint2*)(k + ((size_t)b * NC + kbase + kk) * D + d0));
#pragma unroll
            for (int qi = 0; qi < 8; qi++) {
                float4 qf = *(const float4*)(Qs + qi * 260 + d0);
#pragma unroll
                for (int kk = 0; kk < 4; kk++)
                    s[qi][kk] += dot4(qf, kf[kk]);
            }
        }
        // keys w*32+16+g*4 (second 16-key batch for this warp)
        float s2[8][4];
#pragma unroll
        for (int qi = 0; qi < 8; qi++)
#pragma unroll
            for (int kk = 0; kk < 4; kk++) s2[qi][kk] = 0.f;
#pragma unroll
        for (int c = 0; c < 8; c++) {
            const int d0 = 32 * c + 4 * t;
            float4 kf[4];
#pragma unroll
            for (int kk = 0; kk < 4; kk++)
                kf[kk] = h4f(*(const uint2*)(k + ((size_t)b * NC + kbase + 16 + kk) * D + d0));
#pragma unroll
            for (int qi = 0; qi < 8; qi++) {
                float4 qf = *(const float4*)(Qs + qi * 260 + d0);
#pragma unroll
                for (int kk = 0; kk < 4; kk++)
                    s2[qi][kk] += dot4(qf, kf[kk]);
            }
        }
#pragma unroll
        for (int off = 1; off < 8; off <<= 1)
#pragma unroll
            for (int qi = 0; qi < 8; qi++)
#pragma unroll
                for (int kk = 0; kk < 4; kk++) {
                    s[qi][kk]  += __shfl_xor_sync(0xffffffffu, s[qi][kk],  off);
                    s2[qi][kk] += __shfl_xor_sync(0xffffffffu, s2[qi][kk], off);
                }
        if (t == 0) {
#pragma unroll
            for (int qi = 0; qi < 8; qi++)
#pragma unroll
                for (int kk = 0; kk < 4; kk++) {
                    Ps[qi * 260 + kbase + kk]      = s[qi][kk]  * scale;
                    Ps[qi * 260 + kbase + 16 + kk] = s2[qi][kk] * scale;
                }
        }
    }
    __syncthreads();

    // softmax over 256 keys: warp w handles row w (8 rows, 8 warps)
    {
        float* row = Ps + w * 260;
        float vals[8];
        float mx = -1e30f;
#pragma unroll
        for (int j = 0; j < 8; j++) { vals[j] = row[l + 32*j]; mx = fmaxf(mx, vals[j]); }
#pragma unroll
        for (int o = 16; o > 0; o >>= 1) mx = fmaxf(mx, __shfl_xor_sync(0xffffffffu, mx, o));
        float sum = 0.f;
#pragma unroll
        for (int j = 0; j < 8; j++) { vals[j] = __expf(vals[j] - mx); sum += vals[j]; }
#pragma unroll
        for (int o = 16; o > 0; o >>= 1) sum += __shfl_xor_sync(0xffffffffu, sum, o);
        float inv = 1.f / sum;
#pragma unroll
        for (int j = 0; j < 8; j++) row[l + 32*j] = vals[j] * inv;
    }
    __syncthreads();

    // U = P @ V: warp w = query w; lane l dims 4l..4l+3 and 128+4l..+3
    float4 u0 = make_float4(0,0,0,0), u1 = u0;
    const uint2* vbase = (const uint2*)(v + (size_t)b * NC * D);
    const float* prow = Ps + w * 260;
#pragma unroll 4
    for (int c = 0; c < 256; c++) {
        float p = prow[c];
        float4 vA = h4f(vbase[c * 64 + l]);
        float4 vB = h4f(vbase[c * 64 + 32 + l]);
        u0.x += p * vA.x; u0.y += p * vA.y; u0.z += p * vA.z; u0.w += p * vA.w;
        u1.x += p * vB.x; u1.y += p * vB.y; u1.z += p * vB.z; u1.w += p * vB.w;
    }

    // residual + l2 norm (warp-local)
    const size_t gr = (size_t)(qrow0 + w) * D;
    float4 rA = *(const float4*)(h + gr + 4 * l);
    float4 rB = *(const float4*)(h + gr + 128 + 4 * l);
    rA.x += u0.x; rA.y += u0.y; rA.z += u0.z; rA.w += u0.w;
    rB.x += u1.x; rB.y += u1.y; rB.z += u1.z; rB.w += u1.w;
    float nn = rA.x*rA.x + rA.y*rA.y + rA.z*rA.z + rA.w*rA.w
             + rB.x*rB.x + rB.y*rB.y + rB.z*rB.z + rB.w*rB.w;
#pragma unroll
    for (int o = 16; o > 0; o >>= 1) nn += __shfl_xor_sync(0xffffffffu, nn, o);
    float inv = 1.f / fmaxf(sqrtf(nn), 1e-12f);
    *(float4*)(out + gr + 4 * l) =
        make_float4(rA.x*inv, rA.y*inv, rA.z*inv, rA.w*inv);
    *(float4*)(out + gr + 128 + 4 * l) =
        make_float4(rB.x*inv, rB.y*inv, rB.z*inv, rB.w*inv);
}

// ---------------------------------------------------------------------------
// Cat attention: q = gx_cat, keys = t_ads (+beta2), v = v_ads (unchanged)
// ---------------------------------------------------------------------------
__global__ void __launch_bounds__(256, 2)
attn_cat(const __half* __restrict__ q, const __half* __restrict__ k,
         const __half* __restrict__ v, const float* __restrict__ h,
         const float* __restrict__ beta2, float* __restrict__ out)
{
    extern __shared__ __align__(16) float sm[];
    float* Ks = sm;
    float* Vs = sm + 16 * 260;
    const int tid = threadIdx.x;
    const int b = blockIdx.x >> 3, xp = blockIdx.x & 7;
    const float scale = 0.0625f;

    {
        const uint2* ks = (const uint2*)(k + (size_t)b * (NA * D));
        const uint2* vs = (const uint2*)(v + (size_t)b * (NA * D));
#pragma unroll
        for (int h2 = 0; h2 < 4; h2++) {
            int i = tid + h2 * 256;
            int row = i >> 6, col = (i & 63) << 2;
            float4 kv = h4f(ks[i]);
            float* dk = Ks + row * 260 + col;
            dk[0] = kv.x; dk[1] = kv.y; dk[2] = kv.z; dk[3] = kv.w;
            float4 vv = h4f(vs[i]);
            float* dv = Vs + row * 260 + col;
            dv[0] = vv.x; dv[1] = vv.y; dv[2] = vv.z; dv[3] = vv.w;
        }
    }
    __syncthreads();

    const int w = tid >> 5, l = tid & 31;
    const int g = l >> 3, t = l & 7;
    const int c0 = xp * 32 + w * 4;
    const size_t gr0 = (size_t)b * NC + c0;

    float b2r[4];
#pragma unroll
    for (int kk = 0; kk < 4; kk++)
        b2r[kk] = beta2[(size_t)b * NA + 4 * g + kk];

    float s[4][4];
#pragma unroll
    for (int qi = 0; qi < 4; qi++)
#pragma unroll
        for (int kk = 0; kk < 4; kk++) s[qi][kk] = 0.f;

#pragma unroll
    for (int c = 0; c < 8; c++) {
        const int d0 = 32 * c + 4 * t;
        float4 kf[4];
#pragma unroll
        for (int kk = 0; kk < 4; kk++)
            kf[kk] = *(const float4*)(Ks + (4 * g + kk) * 260 + d0);
#pragma unroll
        for (int qi = 0; qi < 4; qi++) {
            float4 qf = h4f(*(const uint2*)(q + (gr0 + qi) * D + d0));
#pragma unroll
            for (int kk = 0; kk < 4; kk++)
                s[qi][kk] += dot4(qf, kf[kk]);
        }
    }
#pragma unroll
    for (int off = 1; off < 8; off <<= 1)
#pragma unroll
        for (int qi = 0; qi < 4; qi++)
#pragma unroll
            for (int kk = 0; kk < 4; kk++)
                s[qi][kk] += __shfl_xor_sync(0xffffffffu, s[qi][kk], off);
#pragma unroll
    for (int qi = 0; qi < 4; qi++)
#pragma unroll
        for (int kk = 0; kk < 4; kk++)
            s[qi][kk] += b2r[kk];

    float p[4][4];
#pragma unroll
    for (int qi = 0; qi < 4; qi++) {
        float mx = fmaxf(fmaxf(s[qi][0], s[qi][1]), fmaxf(s[qi][2], s[qi][3]));
#pragma unroll
        for (int off = 8; off < 32; off <<= 1)
            mx = fmaxf(mx, __shfl_xor_sync(0xffffffffu, mx, off));
        float sum = 0.f;
#pragma unroll
        for (int kk = 0; kk < 4; kk++) {
            p[qi][kk] = __expf((s[qi][kk] - mx) * scale);
            sum += p[qi][kk];
        }
#pragma unroll
        for (int off = 8; off < 32; off <<= 1)
            sum += __shfl_xor_sync(0xffffffffu, sum, off);
        float inv = 1.f / sum;
#pragma unroll
        for (int kk = 0; kk < 4; kk++) p[qi][kk] *= inv;
    }

    float4 uA[4], uB[4];
#pragma unroll
    for (int qi = 0; qi < 4; qi++) { uA[qi] = make_float4(0,0,0,0); uB[qi] = uA[qi]; }
#pragma unroll
    for (int j = 0; j < 16; j++) {
        const int src = (j >> 2) << 3;
        float pq[4];
#pragma unroll
        for (int qi = 0; qi < 4; qi++)
            pq[qi] = __shfl_sync(0xffffffffu, p[qi][j & 3], src);
        float4 vA = *(const float4*)(Vs + j * 260 + 4 * l);
        float4 vB = *(const float4*)(Vs + j * 260 + 128 + 4 * l);
#pragma unroll
        for (int qi = 0; qi < 4; qi++) {
            uA[qi].x += pq[qi] * vA.x; uA[qi].y += pq[qi] * vA.y;
            uA[qi].z += pq[qi] * vA.z; uA[qi].w += pq[qi] * vA.w;
            uB[qi].x += pq[qi] * vB.x; uB[qi].y += pq[qi] * vB.y;
            uB[qi].z += pq[qi] * vB.z; uB[qi].w += pq[qi] * vB.w;
        }
    }

#pragma unroll
    for (int qi = 0; qi < 4; qi++) {
        const float* hr = h + (gr0 + qi) * D;
        float4 rA = *(const float4*)(hr + 4 * l);
        float4 rB = *(const float4*)(hr + 128 + 4 * l);
        rA.x += uA[qi].x; rA.y += uA[qi].y; rA.z += uA[qi].z; rA.w += uA[qi].w;
        rB.x += uB[qi].x; rB.y += uB[qi].y; rB.z += uB[qi].z; rB.w += uB[qi].w;
        float nn = rA.x*rA.x + rA.y*rA.y + rA.z*rA.z + rA.w*rA.w
                 + rB.x*rB.x + rB.y*rB.y + rB.z*rB.z + rB.w*rB.w;
#pragma unroll
        for (int o = 16; o > 0; o >>= 1) nn += __shfl_xor_sync(0xffffffffu, nn, o);
        float inv = 1.f / fmaxf(sqrtf(nn), 1e-12f);
        float* orow = out + (gr0 + qi) * D;
        *(float4*)(orow + 4 * l) =
            make_float4(rA.x*inv, rA.y*inv, rA.z*inv, rA.w*inv);
        *(float4*)(orow + 128 + 4 * l) =
            make_float4(rB.x*inv, rB.y*inv, rB.z*inv, rB.w*inv);
    }
}

// ---------------------------------------------------------------------------
// Launch
// ---------------------------------------------------------------------------
extern "C" void kernel_launch(void* const* d_in, const int* in_sizes, int n_in,
                              void* d_out, int out_size)
{
    const float* h_ads = (const float*)d_in[0];
    const float* h_cat = (const float*)d_in[1];
    const float* Wq_a = (const float*)d_in[2];  const float* bq_a = (const float*)d_in[3];
    const float* Wk_a = (const float*)d_in[4];
    const float* Wv_a = (const float*)d_in[6];  const float* bv_a = (const float*)d_in[7];
    const float* Wq_c = (const float*)d_in[8];  const float* bq_c = (const float*)d_in[9];
    const float* Wk_c = (const float*)d_in[10];
    const float* Wv_c = (const float*)d_in[12]; const float* bv_c = (const float*)d_in[13];

    const int M_ads = in_sizes[0] / D;   // 8192
    const int M_cat = in_sizes[1] / D;   // 131072
    const int B     = M_ads / NA;        // 512

    __half *qm, *tads, *vads, *vcat, *xah, *xch, *wv, *w1h, *w2h;
    float *w1, *w2, *zerob, *beta2;
    cudaGetSymbolAddress((void**)&qm,    g_qads);
    cudaGetSymbolAddress((void**)&tads,  g_tads);
    cudaGetSymbolAddress((void**)&vads,  g_vads);
    cudaGetSymbolAddress((void**)&vcat,  g_vcat);
    cudaGetSymbolAddress((void**)&xah,   gx_ads);
    cudaGetSymbolAddress((void**)&xch,   gx_cat);
    cudaGetSymbolAddress((void**)&wv,    gw_v);
    cudaGetSymbolAddress((void**)&w1h,   gW1h);
    cudaGetSymbolAddress((void**)&w2h,   gW2h);
    cudaGetSymbolAddress((void**)&w1,    g_w1);
    cudaGetSymbolAddress((void**)&w2,    g_w2);
    cudaGetSymbolAddress((void**)&zerob, g_zero);
    cudaGetSymbolAddress((void**)&beta2, g_beta2);

    conv_all<<<4096, 256>>>((const float4*)h_ads, (uint2*)xah, M_ads * D / 4,
                            (const float4*)h_cat, (uint2*)xch, M_cat * D / 4);
    conv_w<<<dim3(64, 2), 256>>>(Wv_a, Wv_c, (uint2*)wv);

    WprodArgs wa;
    wa.A[0] = Wk_c; wa.B[0] = Wq_a; wa.bA[0] = bq_a; wa.wA[0] = w1;
    wa.bB[0] = nullptr; wa.wB[0] = nullptr; wa.P[0] = w1h;
    wa.A[1] = Wq_c; wa.B[1] = Wk_a; wa.bA[1] = nullptr; wa.wA[1] = nullptr;
    wa.bB[1] = bq_c; wa.wB[1] = w2; wa.P[1] = w2h;
    wprod2<<<dim3(256, 2), 256>>>(wa);

    beta2_kernel<<<M_ads / 8, 256>>>(xah, w2, beta2);

    GemmArgs ga;
    ga.X[0] = xah; ga.X[1] = xah; ga.X[2] = xah; ga.X[3] = xch;
    ga.W[0] = w1h; ga.W[1] = w2h; ga.W[2] = wv;  ga.W[3] = wv + 65536;
    ga.bias[0] = w1; ga.bias[1] = zerob; ga.bias[2] = bv_a; ga.bias[3] = bv_c;
    ga.Y[0] = qm; ga.Y[1] = tads; ga.Y[2] = vads; ga.Y[3] = vcat;

    const int gemm_smem = 3 * SSTAGE;
    cudaFuncSetAttribute((const void*)gemm_pipe,
                         cudaFuncAttributeMaxDynamicSharedMemorySize, gemm_smem);
    gemm_pipe<<<dim3(192 + M_cat / 128, 2), 256, gemm_smem>>>(ga);

    const int cat_smem = 2 * 16 * 260 * 4;
    const int ads_smem = 2 * 8 * 260 * 4;
    cudaFuncSetAttribute((const void*)attn_ads,
                         cudaFuncAttributeMaxDynamicSharedMemorySize, ads_smem);
    cudaFuncSetAttribute((const void*)attn_cat,
                         cudaFuncAttributeMaxDynamicSharedMemorySize, cat_smem);

    attn_cat<<<8 * B, 256, cat_smem>>>(xch, tads, vads, h_cat, beta2,
                                       (float*)d_out + (size_t)M_ads * D);
    attn_ads<<<2 * B, 256, ads_smem>>>(qm, xch, vcat, h_ads, (float*)d_out);
}

// round 17
// speedup vs baseline: 1.1324x; 1.1324x over previous
#include <cuda_runtime.h>
#include <cuda_fp16.h>
#include <math.h>
#include <stdint.h>

#define D   256
#define NA  16
#define NC  256

// ---------------------------------------------------------------------------
// Scratch (device globals — no allocation allowed in kernel_launch)
// ---------------------------------------------------------------------------
__device__ __half g_qads[8192u  * 256u];   // qm_ads = h_ads@G1 + w1
__device__ __half g_tads[8192u  * 256u];   // t_ads  = h_ads@G2
__device__ __half g_vads[8192u  * 256u];
__device__ __half g_vcat[131072u * 256u];
__device__ __half gx_ads[8192u  * 256u];
__device__ __half gx_cat[131072u * 256u];
__device__ __half gw_v[2u * 65536u];       // Wv_a, Wv_c fp16
__device__ __half gW1h[65536u];            // W1[m,j] = sum_i Wk_c[i,m] Wq_a[i,j]
__device__ __half gW2h[65536u];            // W2[m,j] = sum_i Wq_c[i,m] Wk_a[i,j]
__device__ float  g_w1[256];               // w1[m] = sum_i bq_a[i] Wk_c[i,m]
__device__ float  g_w2[256];               // w2[j] = sum_i bq_c[i] Wk_a[i,j]
__device__ float  g_zero[256];             // zero bias (static zero-init)
__device__ float  g_beta2[8192];           // beta2[a] = h_a . w2

struct GemmArgs {
    const __half* X[4];
    const __half* W[4];
    const float*  bias[4];
    __half*       Y[4];
};
struct WprodArgs {
    const float* A[2];
    const float* B[2];
    const float* bA[2];
    float*       wA[2];
    const float* bB[2];
    float*       wB[2];
    __half*      P[2];
};

// ---------------------------------------------------------------------------
// PTX helpers (arch-neutral sm_80+ — harness ptxas target is plain sm_103)
// ---------------------------------------------------------------------------
__device__ __forceinline__ uint32_t smem_u32(const void* p) {
    uint32_t a;
    asm("{ .reg .u64 t; cvta.to.shared.u64 t, %1; cvt.u32.u64 %0, t; }"
        : "=r"(a) : "l"(p));
    return a;
}
__device__ __forceinline__ void cpa16(uint32_t dst, const void* src) {
    asm volatile("cp.async.ca.shared.global [%0], [%1], 16;"
                 :: "r"(dst), "l"(src) : "memory");
}
__device__ __forceinline__ void ldm_x4(uint32_t* r, uint32_t addr) {
    asm volatile("ldmatrix.sync.aligned.m8n8.x4.shared.b16 {%0,%1,%2,%3}, [%4];"
                 : "=r"(r[0]), "=r"(r[1]), "=r"(r[2]), "=r"(r[3]) : "r"(addr));
}
__device__ __forceinline__ void mma16816h(float* c, const uint32_t* a,
                                          const uint32_t* b) {
    asm volatile(
        "mma.sync.aligned.m16n8k16.row.col.f32.f16.f16.f32 "
        "{%0,%1,%2,%3}, {%4,%5,%6,%7}, {%8,%9}, {%0,%1,%2,%3};"
        : "+f"(c[0]), "+f"(c[1]), "+f"(c[2]), "+f"(c[3])
        : "r"(a[0]), "r"(a[1]), "r"(a[2]), "r"(a[3]), "r"(b[0]), "r"(b[1]));
}
__device__ __forceinline__ uint32_t cvt2h(float a, float b) {
    uint32_t hp;
    asm("cvt.rn.f16x2.f32 %0, %1, %2;" : "=r"(hp) : "f"(b), "f"(a));
    return hp;
}
__device__ __forceinline__ float4 h4f(uint2 v) {
    __half2 h0 = *reinterpret_cast<__half2*>(&v.x);
    __half2 h1 = *reinterpret_cast<__half2*>(&v.y);
    float2 f0 = __half22float2(h0), f1 = __half22float2(h1);
    return make_float4(f0.x, f0.y, f1.x, f1.y);
}
__device__ __forceinline__ float dot4(float4 a, float4 b) {
    return a.x*b.x + a.y*b.y + a.z*b.z + a.w*b.w;
}

// ---------------------------------------------------------------------------
// Conversion prepass (merged ads+cat)
// ---------------------------------------------------------------------------
__global__ void __launch_bounds__(256)
conv_all(const float4* __restrict__ sa, uint2* __restrict__ da, int na4,
         const float4* __restrict__ sc, uint2* __restrict__ dc, int nc4)
{
    const int n = na4 + nc4;
    for (int i = blockIdx.x * blockDim.x + threadIdx.x; i < n;
         i += gridDim.x * blockDim.x) {
        if (i < na4) {
            float4 f = sa[i];
            da[i] = make_uint2(cvt2h(f.x, f.y), cvt2h(f.z, f.w));
        } else {
            float4 f = sc[i - na4];
            dc[i - na4] = make_uint2(cvt2h(f.x, f.y), cvt2h(f.z, f.w));
        }
    }
}

__global__ void __launch_bounds__(256)
conv_w(const float* w0, const float* w1, uint2* __restrict__ hi)
{
    const int z = blockIdx.y;
    const float* W = (z == 0) ? w0 : w1;
    const int i = blockIdx.x * 256 + threadIdx.x;
    float4 f = ((const float4*)W)[i];
    hi[z * 16384 + i] = make_uint2(cvt2h(f.x, f.y), cvt2h(f.z, f.w));
}

// ---------------------------------------------------------------------------
// Weight-products (both fused): P[m,j] = sum_i A[i,m] * B[i,j]
// ---------------------------------------------------------------------------
__global__ void __launch_bounds__(256)
wprod2(WprodArgs wa)
{
    const int z = blockIdx.y;
    const float* __restrict__ A = wa.A[z];
    const float* __restrict__ B = wa.B[z];
    __shared__ float As[256];
    const int m = blockIdx.x, j = threadIdx.x;

    As[j] = A[(size_t)j * 256 + m];
    __syncthreads();

    float a0 = 0.f, a1 = 0.f, a2 = 0.f, a3 = 0.f;
#pragma unroll 8
    for (int i = 0; i < 256; i += 4) {
        a0 += As[i]     * B[(size_t)i * 256 + j];
        a1 += As[i + 1] * B[(size_t)(i + 1) * 256 + j];
        a2 += As[i + 2] * B[(size_t)(i + 2) * 256 + j];
        a3 += As[i + 3] * B[(size_t)(i + 3) * 256 + j];
    }
    wa.P[z][(size_t)m * 256 + j] = __float2half((a0 + a1) + (a2 + a3));

    if (wa.wA[z] && j == 0) {
        const float* bA = wa.bA[z];
        float s = 0.f;
        for (int i = 0; i < 256; i++) s += bA[i] * As[i];
        wa.wA[z][m] = s;
    }
    if (wa.wB[z] && m == 0) {
        const float* bB = wa.bB[z];
        float s0 = 0.f, s1 = 0.f, s2 = 0.f, s3 = 0.f;
#pragma unroll 8
        for (int i = 0; i < 256; i += 4) {
            s0 += bB[i]     * B[(size_t)i * 256 + j];
            s1 += bB[i + 1] * B[(size_t)(i + 1) * 256 + j];
            s2 += bB[i + 2] * B[(size_t)(i + 2) * 256 + j];
            s3 += bB[i + 3] * B[(size_t)(i + 3) * 256 + j];
        }
        wa.wB[z][j] = (s0 + s1) + (s2 + s3);
    }
}

// ---------------------------------------------------------------------------
// beta2[a] = h_ads[a] . w2   (warp per row)
// ---------------------------------------------------------------------------
__global__ void __launch_bounds__(256)
beta2_kernel(const __half* __restrict__ x, const float* __restrict__ w2,
             float* __restrict__ beta2)
{
    const int warp = threadIdx.x >> 5, l = threadIdx.x & 31;
    const int row = blockIdx.x * 8 + warp;
    const uint2* xr = (const uint2*)(x + (size_t)row * 256);
    float4 a = h4f(xr[l]), b = h4f(xr[32 + l]);
    float4 wa = *(const float4*)(w2 + 4 * l);
    float4 wb = *(const float4*)(w2 + 128 + 4 * l);
    float s = dot4(a, wa) + dot4(b, wb);
#pragma unroll
    for (int o = 16; o > 0; o >>= 1) s += __shfl_xor_sync(0xffffffffu, s, o);
    if (l == 0) beta2[row] = s;
}

// ---------------------------------------------------------------------------
// Pipelined fp16 GEMM (4 fused problems: qm_ads / t_ads / v_ads / v_cat)
// ---------------------------------------------------------------------------
#define SMAT   16384u
#define SSTAGE 32768u
#define SWZ(row, ch) ((uint32_t)(row) * 128u + (((uint32_t)((ch) ^ ((row) & 7)) & 7u) << 4))

__global__ void __launch_bounds__(256, 2)
gemm_pipe(GemmArgs args)
{
    const int x    = blockIdx.x;
    const int widx = (x < 192) ? (x >> 6) : 3;
    const int mt   = (x < 192) ? (x & 63) : (x - 192);
    const __half* Xh   = args.X[widx];
    const __half* Whi  = args.W[widx];
    const float*  bias = args.bias[widx];
    __half*       Y    = args.Y[widx];

    extern __shared__ __align__(16) char smraw[];
    const uint32_t sb = smem_u32(smraw);

    const int tid  = threadIdx.x;
    const int lane = tid & 31;
    const int wid  = tid >> 5;
    const int wm   = wid & 3;
    const int wn   = wid >> 2;
    const int m0   = mt * 128;
    const int n0   = blockIdx.y * 128;

    float acc[2][8][4];
#pragma unroll
    for (int i = 0; i < 2; i++)
#pragma unroll
        for (int j = 0; j < 8; j++)
#pragma unroll
            for (int t = 0; t < 4; t++) acc[i][j][t] = 0.f;

#define ISSUE(stage, kk)                                                          \
    do {                                                                          \
        const uint32_t s = sb + (stage) * SSTAGE;                                 \
        _Pragma("unroll")                                                         \
        for (int i = 0; i < 4; i++) {                                             \
            const int idx = tid + 256 * i;                                        \
            const int row = idx >> 3, ch = idx & 7;                               \
            const uint32_t d = SWZ(row, ch);                                      \
            cpa16(s + 0*SMAT + d, Xh  + (size_t)(m0 + row) * 256 + (kk) + ch * 8);\
            cpa16(s + 1*SMAT + d, Whi + (size_t)(n0 + row) * 256 + (kk) + ch * 8);\
        }                                                                         \
        asm volatile("cp.async.commit_group;" ::: "memory");                      \
    } while (0)

    const int l15 = lane & 15, lhi = lane >> 4;
    uint32_t arowb[2], axor[2], browb[4], bxor[4];
#pragma unroll
    for (int i = 0; i < 2; i++) {
        uint32_t r = (uint32_t)(wm * 32 + i * 16 + l15);
        arowb[i] = r * 128u;
        axor[i] = r & 7u;
    }
#pragma unroll
    for (int bp = 0; bp < 4; bp++) {
        uint32_t r = (uint32_t)(wn * 64 + bp * 16 + l15);
        browb[bp] = r * 128u;
        bxor[bp] = r & 7u;
    }

    ISSUE(0, 0);
    ISSUE(1, 64);

#pragma unroll 1
    for (int c = 0; c < 4; c++) {
        if (c < 3)
            asm volatile("cp.async.wait_group 1;" ::: "memory");
        else
            asm volatile("cp.async.wait_group 0;" ::: "memory");
        __syncthreads();
        if (c + 2 < 4) ISSUE((c + 2) % 3, (c + 2) * 64);

        const uint32_t st = sb + (uint32_t)(c % 3) * SSTAGE;
#pragma unroll
        for (int ks = 0; ks < 4; ks++) {
            const uint32_t cb = (uint32_t)(ks * 2 + lhi);
            uint32_t ah[2][4], b[8][2], r[4];

#pragma unroll
            for (int i = 0; i < 2; i++)
                ldm_x4(ah[i], st + 0*SMAT + arowb[i] + (((cb ^ axor[i]) & 7u) << 4));
#pragma unroll
            for (int bp = 0; bp < 4; bp++) {
                ldm_x4(r, st + 1*SMAT + browb[bp] + (((cb ^ bxor[bp]) & 7u) << 4));
                b[2*bp][0] = r[0]; b[2*bp+1][0] = r[1];
                b[2*bp][1] = r[2]; b[2*bp+1][1] = r[3];
            }
#pragma unroll
            for (int am = 0; am < 2; am++)
#pragma unroll
                for (int bn = 0; bn < 8; bn++) mma16816h(acc[am][bn], ah[am], b[bn]);
        }
    }

    const int orow  = m0 + wm * 32 + (lane >> 2);
    const int ocol0 = n0 + wn * 64 + (lane & 3) * 2;
#pragma unroll
    for (int am = 0; am < 2; am++) {
#pragma unroll
        for (int bn = 0; bn < 8; bn++) {
            const int col = ocol0 + bn * 8;
            float2 bv = *(const float2*)(bias + col);
            uint32_t p0 = cvt2h(acc[am][bn][0] + bv.x, acc[am][bn][1] + bv.y);
            uint32_t p1 = cvt2h(acc[am][bn][2] + bv.x, acc[am][bn][3] + bv.y);
            *(uint32_t*)(Y + (size_t)(orow + am * 16)     * 256 + col) = p0;
            *(uint32_t*)(Y + (size_t)(orow + am * 16 + 8) * 256 + col) = p1;
        }
    }
}

// ---------------------------------------------------------------------------
// Ads attention (R15 form): 1 block/graph, 16 queries, fp16 residual source.
// ---------------------------------------------------------------------------
__global__ void __launch_bounds__(256, 2)
attn_ads(const __half* __restrict__ q, const __half* __restrict__ k,
         const __half* __restrict__ v, const __half* __restrict__ hx,
         float* __restrict__ out)
{
    extern __shared__ __align__(16) float sm[];
    float* Qs = sm;             // 16 x 260
    float* Ps = sm + 16 * 260;  // 16 x 260
    const int b   = blockIdx.x;
    const int tid = threadIdx.x;
    const float scale = 0.0625f;

    {
        const uint2* src = (const uint2*)(q + (size_t)b * (NA * D));
#pragma unroll
        for (int h2 = 0; h2 < 4; h2++) {
            int i = tid + h2 * 256;
            int row = i >> 6, col = (i & 63) << 2;
            float4 vv = h4f(src[i]);
            float* d = Qs + row * 260 + col;
            d[0] = vv.x; d[1] = vv.y; d[2] = vv.z; d[3] = vv.w;
        }
    }
    __syncthreads();

    const int w = tid >> 5, l = tid & 31;
    const int g = l >> 3, t = l & 7;

#pragma unroll 1
    for (int sb2 = 0; sb2 < 2; sb2++) {
        const int kbase = w * 32 + sb2 * 16 + g * 4;
#pragma unroll 1
        for (int qh = 0; qh < 2; qh++) {
            float s[8][4];
#pragma unroll
            for (int qi = 0; qi < 8; qi++)
#pragma unroll
                for (int kk = 0; kk < 4; kk++) s[qi][kk] = 0.f;

#pragma unroll
            for (int c = 0; c < 8; c++) {
                const int d0 = 32 * c + 4 * t;
                float4 kf[4];
#pragma unroll
                for (int kk = 0; kk < 4; kk++)
                    kf[kk] = h4f(*(const uint2*)(k + ((size_t)b * NC + kbase + kk) * D + d0));
#pragma unroll
                for (int qi = 0; qi < 8; qi++) {
                    float4 qf = *(const float4*)(Qs + (qh * 8 + qi) * 260 + d0);
#pragma unroll
                    for (int kk = 0; kk < 4; kk++)
                        s[qi][kk] += dot4(qf, kf[kk]);
                }
            }
#pragma unroll
            for (int off = 1; off < 8; off <<= 1)
#pragma unroll
                for (int qi = 0; qi < 8; qi++)
#pragma unroll
                    for (int kk = 0; kk < 4; kk++)
                        s[qi][kk] += __shfl_xor_sync(0xffffffffu, s[qi][kk], off);
            if (t == 0) {
#pragma unroll
                for (int qi = 0; qi < 8; qi++)
#pragma unroll
                    for (int kk = 0; kk < 4; kk++)
                        Ps[(qh * 8 + qi) * 260 + kbase + kk] = s[qi][kk] * scale;
            }
        }
    }
    __syncthreads();

    {
        for (int r = w; r < 16; r += 8) {
            float* row = Ps + r * 260;
            float vals[8];
            float mx = -1e30f;
#pragma unroll
            for (int j = 0; j < 8; j++) { vals[j] = row[l + 32*j]; mx = fmaxf(mx, vals[j]); }
#pragma unroll
            for (int o = 16; o > 0; o >>= 1) mx = fmaxf(mx, __shfl_xor_sync(0xffffffffu, mx, o));
            float sum = 0.f;
#pragma unroll
            for (int j = 0; j < 8; j++) { vals[j] = __expf(vals[j] - mx); sum += vals[j]; }
#pragma unroll
            for (int o = 16; o > 0; o >>= 1) sum += __shfl_xor_sync(0xffffffffu, sum, o);
            float inv = 1.f / sum;
#pragma unroll
            for (int j = 0; j < 8; j++) row[l + 32*j] = vals[j] * inv;
        }
    }
    __syncthreads();

    const int aq = tid >> 6;
    const int dg = tid & 63;
    float4 u[4];
#pragma unroll
    for (int qi = 0; qi < 4; qi++) u[qi] = make_float4(0,0,0,0);
    const __half* vbase = v + (size_t)b * NC * D + dg * 4;
    const float* prow0 = Ps + (aq * 4) * 260;
#pragma unroll 4
    for (int c = 0; c < 256; c++) {
        float4 vv = h4f(*(const uint2*)(vbase + (size_t)c * D));
#pragma unroll
        for (int qi = 0; qi < 4; qi++) {
            float p = prow0[qi * 260 + c];
            u[qi].x += p * vv.x; u[qi].y += p * vv.y;
            u[qi].z += p * vv.z; u[qi].w += p * vv.w;
        }
    }

    float ssq[4];
#pragma unroll
    for (int qi = 0; qi < 4; qi++) {
        const float4 hv = h4f(*(const uint2*)(hx + ((size_t)b * NA + aq * 4 + qi) * D + dg * 4));
        u[qi].x += hv.x; u[qi].y += hv.y; u[qi].z += hv.z; u[qi].w += hv.w;
        ssq[qi] = u[qi].x*u[qi].x + u[qi].y*u[qi].y + u[qi].z*u[qi].z + u[qi].w*u[qi].w;
    }
#pragma unroll
    for (int off = 16; off > 0; off >>= 1)
#pragma unroll
        for (int qi = 0; qi < 4; qi++)
            ssq[qi] += __shfl_xor_sync(0xffffffffu, ssq[qi], off);
    if (l == 0) {
#pragma unroll
        for (int qi = 0; qi < 4; qi++) Qs[w * 4 + qi] = ssq[qi];
    }
    __syncthreads();
#pragma unroll
    for (int qi = 0; qi < 4; qi++) {
        float tot = Qs[(2 * aq) * 4 + qi] + Qs[(2 * aq + 1) * 4 + qi];
        float inv = 1.f / fmaxf(sqrtf(tot), 1e-12f);
        float4 o;
        o.x = u[qi].x * inv; o.y = u[qi].y * inv;
        o.z = u[qi].z * inv; o.w = u[qi].w * inv;
        *(float4*)(out + ((size_t)b * NA + aq * 4 + qi) * D + dg * 4) = o;
    }
}

// ---------------------------------------------------------------------------
// Cat attention: q = gx_cat, keys = t_ads (+beta2), v = v_ads,
// residual from fp16 gx_cat.
// ---------------------------------------------------------------------------
__global__ void __launch_bounds__(256, 2)
attn_cat(const __half* __restrict__ q, const __half* __restrict__ k,
         const __half* __restrict__ v, const float* __restrict__ beta2,
         float* __restrict__ out)
{
    extern __shared__ __align__(16) float sm[];
    float* Ks = sm;
    float* Vs = sm + 16 * 260;
    const int tid = threadIdx.x;
    const int b = blockIdx.x >> 3, xp = blockIdx.x & 7;
    const float scale = 0.0625f;

    {
        const uint2* ks = (const uint2*)(k + (size_t)b * (NA * D));
        const uint2* vs = (const uint2*)(v + (size_t)b * (NA * D));
#pragma unroll
        for (int h2 = 0; h2 < 4; h2++) {
            int i = tid + h2 * 256;
            int row = i >> 6, col = (i & 63) << 2;
            float4 kv = h4f(ks[i]);
            float* dk = Ks + row * 260 + col;
            dk[0] = kv.x; dk[1] = kv.y; dk[2] = kv.z; dk[3] = kv.w;
            float4 vv = h4f(vs[i]);
            float* dv = Vs + row * 260 + col;
            dv[0] = vv.x; dv[1] = vv.y; dv[2] = vv.z; dv[3] = vv.w;
        }
    }
    __syncthreads();

    const int w = tid >> 5, l = tid & 31;
    const int g = l >> 3, t = l & 7;
    const int c0 = xp * 32 + w * 4;
    const size_t gr0 = (size_t)b * NC + c0;

    float b2r[4];
#pragma unroll
    for (int kk = 0; kk < 4; kk++)
        b2r[kk] = beta2[(size_t)b * NA + 4 * g + kk];

    float s[4][4];
#pragma unroll
    for (int qi = 0; qi < 4; qi++)
#pragma unroll
        for (int kk = 0; kk < 4; kk++) s[qi][kk] = 0.f;

#pragma unroll
    for (int c = 0; c < 8; c++) {
        const int d0 = 32 * c + 4 * t;
        float4 kf[4];
#pragma unroll
        for (int kk = 0; kk < 4; kk++)
            kf[kk] = *(const float4*)(Ks + (4 * g + kk) * 260 + d0);
#pragma unroll
        for (int qi = 0; qi < 4; qi++) {
            float4 qf = h4f(*(const uint2*)(q + (gr0 + qi) * D + d0));
#pragma unroll
            for (int kk = 0; kk < 4; kk++)
                s[qi][kk] += dot4(qf, kf[kk]);
        }
    }
#pragma unroll
    for (int off = 1; off < 8; off <<= 1)
#pragma unroll
        for (int qi = 0; qi < 4; qi++)
#pragma unroll
            for (int kk = 0; kk < 4; kk++)
                s[qi][kk] += __shfl_xor_sync(0xffffffffu, s[qi][kk], off);
#pragma unroll
    for (int qi = 0; qi < 4; qi++)
#pragma unroll
        for (int kk = 0; kk < 4; kk++)
            s[qi][kk] += b2r[kk];

    float p[4][4];
#pragma unroll
    for (int qi = 0; qi < 4; qi++) {
        float mx = fmaxf(fmaxf(s[qi][0], s[qi][1]), fmaxf(s[qi][2], s[qi][3]));
#pragma unroll
        for (int off = 8; off < 32; off <<= 1)
            mx = fmaxf(mx, __shfl_xor_sync(0xffffffffu, mx, off));
        float sum = 0.f;
#pragma unroll
        for (int kk = 0; kk < 4; kk++) {
            p[qi][kk] = __expf((s[qi][kk] - mx) * scale);
            sum += p[qi][kk];
        }
#pragma unroll
        for (int off = 8; off < 32; off <<= 1)
            sum += __shfl_xor_sync(0xffffffffu, sum, off);
        float inv = 1.f / sum;
#pragma unroll
        for (int kk = 0; kk < 4; kk++) p[qi][kk] *= inv;
    }

    float4 uA[4], uB[4];
#pragma unroll
    for (int qi = 0; qi < 4; qi++) { uA[qi] = make_float4(0,0,0,0); uB[qi] = uA[qi]; }
#pragma unroll
    for (int j = 0; j < 16; j++) {
        const int src = (j >> 2) << 3;
        float pq[4];
#pragma unroll
        for (int qi = 0; qi < 4; qi++)
            pq[qi] = __shfl_sync(0xffffffffu, p[qi][j & 3], src);
        float4 vA = *(const float4*)(Vs + j * 260 + 4 * l);
        float4 vB = *(const float4*)(Vs + j * 260 + 128 + 4 * l);
#pragma unroll
        for (int qi = 0; qi < 4; qi++) {
            uA[qi].x += pq[qi] * vA.x; uA[qi].y += pq[qi] * vA.y;
            uA[qi].z += pq[qi] * vA.z; uA[qi].w += pq[qi] * vA.w;
            uB[qi].x += pq[qi] * vB.x; uB[qi].y += pq[qi] * vB.y;
            uB[qi].z += pq[qi] * vB.z; uB[qi].w += pq[qi] * vB.w;
        }
    }

#pragma unroll
    for (int qi = 0; qi < 4; qi++) {
        const __half* hr = q + (gr0 + qi) * D;   // residual from fp16 x
        float4 rA = h4f(*(const uint2*)(hr + 4 * l));
        float4 rB = h4f(*(const uint2*)(hr + 128 + 4 * l));
        rA.x += uA[qi].x; rA.y += uA[qi].y; rA.z += uA[qi].z; rA.w += uA[qi].w;
        rB.x += uB[qi].x; rB.y += uB[qi].y; rB.z += uB[qi].z; rB.w += uB[qi].w;
        float nn = rA.x*rA.x + rA.y*rA.y + rA.z*rA.z + rA.w*rA.w
                 + rB.x*rB.x + rB.y*rB.y + rB.z*rB.z + rB.w*rB.w;
#pragma unroll
        for (int o = 16; o > 0; o >>= 1) nn += __shfl_xor_sync(0xffffffffu, nn, o);
        float inv = 1.f / fmaxf(sqrtf(nn), 1e-12f);
        float* orow = out + (gr0 + qi) * D;
        *(float4*)(orow + 4 * l) =
            make_float4(rA.x*inv, rA.y*inv, rA.z*inv, rA.w*inv);
        *(float4*)(orow + 128 + 4 * l) =
            make_float4(rB.x*inv, rB.y*inv, rB.z*inv, rB.w*inv);
    }
}

// ---------------------------------------------------------------------------
// Launch
// ---------------------------------------------------------------------------
extern "C" void kernel_launch(void* const* d_in, const int* in_sizes, int n_in,
                              void* d_out, int out_size)
{
    const float* h_ads = (const float*)d_in[0];
    const float* h_cat = (const float*)d_in[1];
    const float* Wq_a = (const float*)d_in[2];  const float* bq_a = (const float*)d_in[3];
    const float* Wk_a = (const float*)d_in[4];
    const float* Wv_a = (const float*)d_in[6];  const float* bv_a = (const float*)d_in[7];
    const float* Wq_c = (const float*)d_in[8];  const float* bq_c = (const float*)d_in[9];
    const float* Wk_c = (const float*)d_in[10];
    const float* Wv_c = (const float*)d_in[12]; const float* bv_c = (const float*)d_in[13];

    const int M_ads = in_sizes[0] / D;   // 8192
    const int M_cat = in_sizes[1] / D;   // 131072
    const int B     = M_ads / NA;        // 512

    __half *qm, *tads, *vads, *vcat, *xah, *xch, *wv, *w1h, *w2h;
    float *w1, *w2, *zerob, *beta2;
    cudaGetSymbolAddress((void**)&qm,    g_qads);
    cudaGetSymbolAddress((void**)&tads,  g_tads);
    cudaGetSymbolAddress((void**)&vads,  g_vads);
    cudaGetSymbolAddress((void**)&vcat,  g_vcat);
    cudaGetSymbolAddress((void**)&xah,   gx_ads);
    cudaGetSymbolAddress((void**)&xch,   gx_cat);
    cudaGetSymbolAddress((void**)&wv,    gw_v);
    cudaGetSymbolAddress((void**)&w1h,   gW1h);
    cudaGetSymbolAddress((void**)&w2h,   gW2h);
    cudaGetSymbolAddress((void**)&w1,    g_w1);
    cudaGetSymbolAddress((void**)&w2,    g_w2);
    cudaGetSymbolAddress((void**)&zerob, g_zero);
    cudaGetSymbolAddress((void**)&beta2, g_beta2);

    conv_all<<<4096, 256>>>((const float4*)h_ads, (uint2*)xah, M_ads * D / 4,
                            (const float4*)h_cat, (uint2*)xch, M_cat * D / 4);
    conv_w<<<dim3(64, 2), 256>>>(Wv_a, Wv_c, (uint2*)wv);

    WprodArgs wa;
    wa.A[0] = Wk_c; wa.B[0] = Wq_a; wa.bA[0] = bq_a; wa.wA[0] = w1;
    wa.bB[0] = nullptr; wa.wB[0] = nullptr; wa.P[0] = w1h;
    wa.A[1] = Wq_c; wa.B[1] = Wk_a; wa.bA[1] = nullptr; wa.wA[1] = nullptr;
    wa.bB[1] = bq_c; wa.wB[1] = w2; wa.P[1] = w2h;
    wprod2<<<dim3(256, 2), 256>>>(wa);

    beta2_kernel<<<M_ads / 8, 256>>>(xah, w2, beta2);

    GemmArgs ga;
    ga.X[0] = xah; ga.X[1] = xah; ga.X[2] = xah; ga.X[3] = xch;
    ga.W[0] = w1h; ga.W[1] = w2h; ga.W[2] = wv;  ga.W[3] = wv + 65536;
    ga.bias[0] = w1; ga.bias[1] = zerob; ga.bias[2] = bv_a; ga.bias[3] = bv_c;
    ga.Y[0] = qm; ga.Y[1] = tads; ga.Y[2] = vads; ga.Y[3] = vcat;

    const int gemm_smem = 3 * SSTAGE;
    cudaFuncSetAttribute((const void*)gemm_pipe,
                         cudaFuncAttributeMaxDynamicSharedMemorySize, gemm_smem);
    gemm_pipe<<<dim3(192 + M_cat / 128, 2), 256, gemm_smem>>>(ga);

    const int attn_smem = 2 * 16 * 260 * 4;
    cudaFuncSetAttribute((const void*)attn_ads,
                         cudaFuncAttributeMaxDynamicSharedMemorySize, attn_smem);
    cudaFuncSetAttribute((const void*)attn_cat,
                         cudaFuncAttributeMaxDynamicSharedMemorySize, attn_smem);

    attn_cat<<<8 * B, 256, attn_smem>>>(xch, tads, vads, beta2,
                                        (float*)d_out + (size_t)M_ads * D);
    attn_ads<<<B, 256, attn_smem>>>(qm, xch, vcat, xah, (float*)d_out);
}